// round 1
// baseline (speedup 1.0000x reference)
#include <cuda_runtime.h>

#define N_OFFSETS 72
#define N_STRIPS  71
#define ROWLEN    77
#define MAX_KEEP  16

extern __shared__ unsigned long long s_keys[];

__global__ void __launch_bounds__(1024, 1)
laneatt_nms_kernel(const float* __restrict__ prop,
                   const float* __restrict__ scores,
                   const unsigned* __restrict__ thr_raw,
                   const unsigned* __restrict__ topk_raw,
                   float* __restrict__ out,
                   int n, int npow2, int out_size)
{
    const int tid  = threadIdx.x;
    const int nt   = blockDim.x;
    const int lane = tid & 31;
    const int wid  = tid >> 5;

    __shared__ float s_kxs[MAX_KEEP][N_OFFSETS];
    __shared__ int   s_ks[MAX_KEEP], s_ke[MAX_KEEP], s_kidx[MAX_KEEP];
    __shared__ int   s_kcount;
    __shared__ int   s_done;
    __shared__ unsigned char s_supp[1024];

    // --- decode scalar params (robust to int32 or float32 encoding) ---
    unsigned tb = *thr_raw;
    float thr = (tb < 0x00800000u) ? (float)(int)tb : __uint_as_float(tb);
    unsigned kb = *topk_raw;
    int topk = (kb < 0x00800000u) ? (int)kb : (int)__uint_as_float(kb);
    if (topk > MAX_KEEP) topk = MAX_KEEP;
    if (topk < 0) topk = 0;

    // --- build sort keys: ascending sort => descending score, idx tiebreak ---
    for (int i = tid; i < npow2; i += nt) {
        if (i < n) {
            unsigned sb = __float_as_uint(scores[i]);
            s_keys[i] = ((unsigned long long)(~sb) << 32) | (unsigned)i;
        } else {
            s_keys[i] = ~0ULL;   // pads sort to the end
        }
    }
    if (tid == 0) { s_kcount = 0; s_done = 0; }
    __syncthreads();

    // --- bitonic sort (ascending) in shared memory ---
    for (unsigned k = 2; k <= (unsigned)npow2; k <<= 1) {
        for (unsigned j = k >> 1; j; j >>= 1) {
            for (unsigned i = tid; i < (unsigned)npow2; i += nt) {
                unsigned ixj = i ^ j;
                if (ixj > i) {
                    unsigned long long a = s_keys[i];
                    unsigned long long b = s_keys[ixj];
                    bool up = ((i & k) == 0);
                    if ((a > b) == up) { s_keys[i] = b; s_keys[ixj] = a; }
                }
            }
            __syncthreads();
        }
    }

    // --- greedy NMS over ranked candidates, batched pre-filter + warp-0 resolve ---
    for (int base = 0; base < n; base += nt) {
        if (s_done) break;                 // consistent: read right after a __syncthreads
        int kc0 = s_kcount;

        int c = base + tid;
        bool supp = false;
        if (c < n) {
            int idx = (int)(unsigned)(s_keys[c] & 0xFFFFFFFFu);
            const float* row = prop + (long long)idx * ROWLEN;
            int si = (int)rintf(row[2] * (float)N_STRIPS);
            int ei = min(si + (int)rintf(row[4]) - 1, N_STRIPS);
            for (int m = 0; m < kc0 && !supp; ++m) {
                int ps = max(si, s_ks[m]);
                int pe = min(ei, s_ke[m]);
                if (pe >= ps) {
                    float d = 0.f;
                    for (int k2 = ps; k2 <= pe; ++k2)
                        d += fabsf(row[5 + k2] - s_kxs[m][k2]);
                    if (d / (float)(pe - ps + 1) < thr) supp = true;
                }
            }
        }
        s_supp[tid] = (unsigned char)supp;
        __syncthreads();

        if (wid == 0) {
            int kcount = kc0;
            int lim = min(nt, n - base);
            for (int t = 0; t < lim; ++t) {
                if (kcount >= topk) break;
                if (s_supp[t]) continue;
                int c2 = base + t;
                int idx = (int)(unsigned)(s_keys[c2] & 0xFFFFFFFFu);
                const float* row = prop + (long long)idx * ROWLEN;
                int si = 0, ei = 0;
                if (lane == 0) {
                    si = (int)rintf(row[2] * (float)N_STRIPS);
                    ei = min(si + (int)rintf(row[4]) - 1, N_STRIPS);
                }
                si = __shfl_sync(0xffffffffu, si, 0);
                ei = __shfl_sync(0xffffffffu, ei, 0);

                bool dead = false;
                for (int m = kc0; m < kcount && !dead; ++m) {
                    int ps = max(si, s_ks[m]);
                    int pe = min(ei, s_ke[m]);
                    if (pe >= ps) {
                        float d = 0.f;
                        #pragma unroll
                        for (int k2 = lane; k2 < N_OFFSETS; k2 += 32)
                            if (k2 >= ps && k2 <= pe)
                                d += fabsf(row[5 + k2] - s_kxs[m][k2]);
                        #pragma unroll
                        for (int off = 16; off; off >>= 1)
                            d += __shfl_xor_sync(0xffffffffu, d, off);
                        if (d / (float)(pe - ps + 1) < thr) dead = true;
                    }
                }
                if (!dead) {
                    #pragma unroll
                    for (int k2 = lane; k2 < N_OFFSETS; k2 += 32)
                        s_kxs[kcount][k2] = row[5 + k2];
                    if (lane == 0) {
                        s_ks[kcount]  = si;
                        s_ke[kcount]  = ei;
                        s_kidx[kcount] = idx;
                    }
                    __syncwarp();
                    kcount++;
                }
            }
            if (lane == 0) {
                s_kcount = kcount;
                if (kcount >= topk) s_done = 1;
            }
        }
        __syncthreads();
    }

    // --- emit output: topk rows of (77 proposal floats + score), then num_kept ---
    int nk = min(s_kcount, topk);
    int total = topk * (ROWLEN + 1);
    for (int i = tid; i < out_size; i += nt) {
        float v = 0.f;
        if (i < total) {
            int r = i / (ROWLEN + 1);
            int cdx = i % (ROWLEN + 1);
            if (r < nk) {
                int idx = s_kidx[r];
                if (cdx < ROWLEN) v = prop[(long long)idx * ROWLEN + cdx];
                else              v = scores[idx];
            }
        } else if (i == total) {
            v = (float)nk;
        }
        out[i] = v;
    }
}

extern "C" void kernel_launch(void* const* d_in, const int* in_sizes, int n_in,
                              void* d_out, int out_size)
{
    const float*    prop   = (const float*)d_in[0];
    const float*    scores = (const float*)d_in[1];
    const unsigned* thr    = (const unsigned*)d_in[2];
    const unsigned* topk   = (const unsigned*)d_in[3];

    int n = in_sizes[1];                 // number of proposals (scores count)
    int npow2 = 1;
    while (npow2 < n) npow2 <<= 1;
    size_t smem = (size_t)npow2 * sizeof(unsigned long long);

    cudaFuncSetAttribute(laneatt_nms_kernel,
                         cudaFuncAttributeMaxDynamicSharedMemorySize, (int)smem);

    laneatt_nms_kernel<<<1, 1024, smem>>>(prop, scores, thr, topk,
                                          (float*)d_out, n, npow2, out_size);
}

// round 2
// speedup vs baseline: 7.5695x; 7.5695x over previous
#include <cuda_runtime.h>

#define N_OFFSETS 72
#define N_STRIPS  71
#define ROWLEN    77
#define MAX_KEEP  16
#define NTHREADS  1024
#define NWARPS    (NTHREADS / 32)

extern __shared__ unsigned long long s_keys[];   // [n] packed (ord<<32)|~idx

__global__ void __launch_bounds__(NTHREADS, 1)
laneatt_nms_kernel(const float* __restrict__ prop,
                   const float* __restrict__ scores,
                   const unsigned* __restrict__ thr_raw,
                   const unsigned* __restrict__ topk_raw,
                   float* __restrict__ out,
                   int n, int out_size)
{
    const int tid  = threadIdx.x;
    const int lane = tid & 31;
    const int wid  = tid >> 5;

    __shared__ float s_kxs[MAX_KEEP][N_OFFSETS];
    __shared__ int   s_ks[MAX_KEEP], s_ke[MAX_KEEP], s_kidx[MAX_KEEP];
    __shared__ unsigned long long s_wmax[NWARPS];
    __shared__ unsigned long long s_best;
    __shared__ int s_ctrl;          // 0 = continue, 1 = stop
    __shared__ int s_kcount;

    // --- decode scalar params (robust to int32 or float32 encoding) ---
    unsigned tb = *thr_raw;
    float thr = (tb < 0x00800000u) ? (float)(int)tb : __uint_as_float(tb);
    unsigned kb = *topk_raw;
    int topk = (kb < 0x00800000u) ? (int)kb : (int)__uint_as_float(kb);
    if (topk > MAX_KEEP) topk = MAX_KEEP;
    if (topk < 0) topk = 0;

    // --- build keys: max-key == (highest score, lowest index) ---
    for (int i = tid; i < n; i += NTHREADS) {
        unsigned b = __float_as_uint(scores[i]);
        unsigned ord = b ^ ((b >> 31) ? 0xFFFFFFFFu : 0x80000000u); // ascending float order
        s_keys[i] = ((unsigned long long)ord << 32) | (unsigned)(~i);
    }
    if (tid == 0) { s_ctrl = (topk == 0) ? 1 : 0; s_kcount = 0; }
    __syncthreads();

    // --- lazy greedy: repeated argmax over alive keys ---
    while (s_ctrl == 0) {
        // 1) parallel max-reduce over s_keys
        unsigned long long best = 0ULL;
        for (int i = tid; i < n; i += NTHREADS) {
            unsigned long long k = s_keys[i];
            if (k > best) best = k;
        }
        #pragma unroll
        for (int off = 16; off; off >>= 1) {
            unsigned long long o = __shfl_xor_sync(0xffffffffu, best, off);
            if (o > best) best = o;
        }
        if (lane == 0) s_wmax[wid] = best;
        __syncthreads();

        // 2) warp 0 finalizes max + resolves the candidate
        if (wid == 0) {
            unsigned long long b = (lane < NWARPS) ? s_wmax[lane] : 0ULL;
            #pragma unroll
            for (int off = 16; off; off >>= 1) {
                unsigned long long o = __shfl_xor_sync(0xffffffffu, b, off);
                if (o > b) b = o;
            }
            b = __shfl_sync(0xffffffffu, b, 0);

            if (b == 0ULL) {
                if (lane == 0) s_ctrl = 1;       // alive set exhausted
            } else {
                int idx = (int)(~(unsigned)(b & 0xFFFFFFFFu));
                const float* row = prop + (long long)idx * ROWLEN;

                // candidate xs into warp registers (72 = 32 + 32 + 8)
                float x0 = row[5 + lane];
                float x1 = row[37 + lane];
                float x2 = (lane < 8) ? row[69 + lane] : 0.f;

                int si = 0, ei = 0;
                if (lane == 0) {
                    si = (int)rintf(row[2] * (float)N_STRIPS);
                    ei = min(si + (int)rintf(row[4]) - 1, N_STRIPS);
                }
                si = __shfl_sync(0xffffffffu, si, 0);
                ei = __shfl_sync(0xffffffffu, ei, 0);

                int kc = s_kcount;
                bool dead = false;
                for (int m = 0; m < kc && !dead; ++m) {
                    int ps = max(si, s_ks[m]);
                    int pe = min(ei, s_ke[m]);
                    if (pe >= ps) {
                        float d = 0.f;
                        int k2 = lane;
                        if (k2 >= ps && k2 <= pe) d += fabsf(x0 - s_kxs[m][k2]);
                        k2 = lane + 32;
                        if (k2 >= ps && k2 <= pe) d += fabsf(x1 - s_kxs[m][k2]);
                        k2 = lane + 64;
                        if (lane < 8 && k2 >= ps && k2 <= pe) d += fabsf(x2 - s_kxs[m][k2]);
                        #pragma unroll
                        for (int off = 16; off; off >>= 1)
                            d += __shfl_xor_sync(0xffffffffu, d, off);
                        int su = 0;
                        if (lane == 0)
                            su = (d / (float)(pe - ps + 1) < thr) ? 1 : 0;
                        dead = __shfl_sync(0xffffffffu, su, 0);
                    }
                }

                if (!dead) {
                    s_kxs[kc][lane]      = x0;
                    s_kxs[kc][lane + 32] = x1;
                    if (lane < 8) s_kxs[kc][lane + 64] = x2;
                    if (lane == 0) {
                        s_ks[kc]   = si;
                        s_ke[kc]   = ei;
                        s_kidx[kc] = idx;
                        s_kcount   = kc + 1;
                        if (kc + 1 >= topk) s_ctrl = 1;
                    }
                }
                if (lane == 0) s_keys[idx] = 0ULL;   // kill candidate
            }
        }
        __syncthreads();
    }

    // --- emit output: topk rows of (77 proposal floats + score), then num_kept ---
    int nk = min(s_kcount, topk);
    int total = topk * (ROWLEN + 1);
    for (int i = tid; i < out_size; i += NTHREADS) {
        float v = 0.f;
        if (i < total) {
            int r   = i / (ROWLEN + 1);
            int cdx = i % (ROWLEN + 1);
            if (r < nk) {
                int idx = s_kidx[r];
                if (cdx < ROWLEN) v = prop[(long long)idx * ROWLEN + cdx];
                else              v = scores[idx];
            }
        } else if (i == total) {
            v = (float)nk;
        }
        out[i] = v;
    }
}

extern "C" void kernel_launch(void* const* d_in, const int* in_sizes, int n_in,
                              void* d_out, int out_size)
{
    const float*    prop   = (const float*)d_in[0];
    const float*    scores = (const float*)d_in[1];
    const unsigned* thr    = (const unsigned*)d_in[2];
    const unsigned* topk   = (const unsigned*)d_in[3];

    int n = in_sizes[1];                 // number of proposals (scores count)
    size_t smem = (size_t)n * sizeof(unsigned long long);

    cudaFuncSetAttribute(laneatt_nms_kernel,
                         cudaFuncAttributeMaxDynamicSharedMemorySize, (int)smem);

    laneatt_nms_kernel<<<1, NTHREADS, smem>>>(prop, scores, thr, topk,
                                              (float*)d_out, n, out_size);
}

// round 3
// speedup vs baseline: 8.2877x; 1.0949x over previous
#include <cuda_runtime.h>

#define N_OFFSETS 72
#define N_STRIPS  71
#define ROWLEN    77
#define MAX_KEEP  16
#define NL        32          // partitions / merge lists
#define TOPL      32          // sorted entries kept per partition
#define PREF      4           // rows prefetched per list
#define RPAD      80          // padded row stride in smem floats
#define K2T       1024
#define NW        (K2T/32)
#define FULLM     0xffffffffu

__device__ unsigned long long g_top[NL * TOPL];

extern __shared__ unsigned char s_dyn[];

static __device__ __forceinline__ unsigned long long pack_key(float s, int i) {
    unsigned b = __float_as_uint(s);
    unsigned ord = b ^ ((b >> 31) ? 0xFFFFFFFFu : 0x80000000u);  // ascending float order
    return ((unsigned long long)ord << 32) | (unsigned)(~i);     // lower idx wins ties
}

// ---------------- K1: per-partition bitonic sort, emit sorted top-32 ----------------
__global__ void __launch_bounds__(256, 1)
k1_partsort(const float* __restrict__ scores, int n, int chunk, int P)
{
    unsigned long long* sk = (unsigned long long*)s_dyn;   // [P]
    int p = blockIdx.x, tid = threadIdx.x;
    int base = p * chunk;
    for (int i = tid; i < P; i += 256) {
        int gi = base + i;
        sk[i] = (i < chunk && gi < n) ? pack_key(scores[gi], gi) : 0ULL;
    }
    __syncthreads();
    for (unsigned k = 2; k <= (unsigned)P; k <<= 1) {
        for (unsigned j = k >> 1; j; j >>= 1) {
            for (unsigned i = tid; i < (unsigned)P; i += 256) {
                unsigned ixj = i ^ j;
                if (ixj > i) {
                    unsigned long long a = sk[i], b = sk[ixj];
                    if ((a > b) == ((i & k) == 0)) { sk[i] = b; sk[ixj] = a; }
                }
            }
            __syncthreads();
        }
    }
    // ascending array -> top-TOPL descending
    for (int r = tid; r < TOPL; r += 256) {
        int src = P - 1 - r;
        g_top[p * TOPL + r] = (src >= 0) ? sk[src] : 0ULL;
    }
}

// ---------------- K2: prefetch + single-warp lazy merge greedy + fallback ----------------
__global__ void __launch_bounds__(K2T, 1)
k2_greedy(const float* __restrict__ prop, const float* __restrict__ scores,
          const unsigned* __restrict__ thr_raw, const unsigned* __restrict__ topk_raw,
          float* __restrict__ out, int n, int out_size)
{
    unsigned long long* s_keys  = (unsigned long long*)s_dyn;       // [n] (fallback only)
    unsigned long long* s_lists = s_keys + n;                       // [NL*TOPL]
    float* s_rows  = (float*)(s_lists + NL * TOPL);                 // [NL*PREF*RPAD]
    float* s_odrow = s_rows + NL * PREF * RPAD;                     // [RPAD] on-demand scratch

    __shared__ float s_kxs[MAX_KEEP][N_OFFSETS];
    __shared__ int   s_ks[MAX_KEEP], s_ke[MAX_KEEP], s_kidx[MAX_KEEP];
    __shared__ int2  s_se[NL * PREF];
    __shared__ int   s_ptr[NL];
    __shared__ int   s_kcount, s_ctrl, s_fallback;
    __shared__ unsigned long long s_wmax[NW];

    const int tid = threadIdx.x, lane = tid & 31, w = tid >> 5;

    // scalar params (robust to int32 or float32 encoding)
    unsigned tb = *thr_raw;
    float thr = (tb < 0x00800000u) ? (float)(int)tb : __uint_as_float(tb);
    unsigned kb = *topk_raw;
    int topk = (kb < 0x00800000u) ? (int)kb : (int)__uint_as_float(kb);
    topk = min(max(topk, 0), MAX_KEEP);

    // ---- Phase A: copy lists, prefetch top-PREF rows per list, precompute si/ei ----
    for (int i = tid; i < NL * TOPL; i += K2T) s_lists[i] = g_top[i];
    __syncthreads();
    #pragma unroll
    for (int d = 0; d < PREF; ++d) {
        unsigned long long key = s_lists[w * TOPL + d];
        if (key) {
            int idx = ~(unsigned)(key & 0xFFFFFFFFu);
            const float* row = prop + (long long)idx * ROWLEN;
            for (int c = lane; c < ROWLEN; c += 32)
                s_rows[(w * PREF + d) * RPAD + c] = row[c];
        }
    }
    __syncwarp();
    if (lane < PREF) {
        unsigned long long key = s_lists[w * TOPL + lane];
        int2 se = make_int2(0, -1);
        if (key) {
            float y = s_rows[(w * PREF + lane) * RPAD + 2];
            float L = s_rows[(w * PREF + lane) * RPAD + 4];
            int si = (int)rintf(y * (float)N_STRIPS);
            int ei = min(si + (int)rintf(L) - 1, N_STRIPS);
            se = make_int2(si, ei);
        }
        s_se[w * PREF + lane] = se;
    }
    if (tid == 0) { s_kcount = 0; s_ctrl = 1; s_fallback = 0; }
    __syncthreads();

    // ---- Phase B: warp 0 lazy-merge greedy (no block barriers) ----
    if (w == 0) {
        int ptr = 0;
        unsigned long long h = s_lists[lane * TOPL];   // lane == list id
        bool unsafe = false;
        int kc = 0, fb = 0;
        while (kc < topk) {
            if (__ballot_sync(FULLM, unsafe)) { fb = 1; break; }   // merge order no longer provable
            unsigned long long b = h;
            #pragma unroll
            for (int off = 16; off; off >>= 1) {
                unsigned long long o = __shfl_xor_sync(FULLM, b, off);
                if (o > b) b = o;
            }
            if (b == 0ULL) break;                                   // all candidates safely exhausted
            unsigned wm = __ballot_sync(FULLM, h == b);
            int ws = __ffs(wm) - 1;
            int dsel = __shfl_sync(FULLM, ptr, ws);
            int idx = ~(unsigned)(b & 0xFFFFFFFFu);

            const float* crow; int si, ei;
            if (dsel < PREF) {
                crow = &s_rows[(ws * PREF + dsel) * RPAD];
                int2 se = s_se[ws * PREF + dsel];
                si = se.x; ei = se.y;
            } else {
                const float* grow = prop + (long long)idx * ROWLEN;
                for (int c = lane; c < ROWLEN; c += 32) s_odrow[c] = grow[c];
                __syncwarp();
                crow = s_odrow;
                si = (int)rintf(crow[2] * (float)N_STRIPS);
                ei = min(si + (int)rintf(crow[4]) - 1, N_STRIPS);
            }

            // suppression vs kept: lanes = (m, offset-group)
            bool dead = false;
            for (int mb = 0; mb < kc; mb += 8) {
                int m = mb + (lane >> 2);
                int g = lane & 3;
                float dsum = 0.f;
                int ps = 0, pe = -1;
                if (m < kc) {
                    ps = max(si, s_ks[m]); pe = min(ei, s_ke[m]);
                    for (int k = ps + g; k <= pe; k += 4)
                        dsum += fabsf(crow[5 + k] - s_kxs[m][k]);
                }
                dsum += __shfl_xor_sync(FULLM, dsum, 1);
                dsum += __shfl_xor_sync(FULLM, dsum, 2);
                bool sup = (m < kc) && (pe >= ps) && (dsum / (float)(pe - ps + 1) < thr);
                if (__ballot_sync(FULLM, sup)) { dead = true; break; }
            }

            if (!dead) {
                for (int k = lane; k < N_OFFSETS; k += 32) s_kxs[kc][k] = crow[5 + k];
                if (lane == 0) { s_ks[kc] = si; s_ke[kc] = ei; s_kidx[kc] = idx; }
                __syncwarp();
                kc++;
            }
            if (lane == ws) {
                ptr++;
                if (ptr < TOPL) h = s_lists[lane * TOPL + ptr];
                else {
                    h = 0ULL;
                    if (s_lists[lane * TOPL + TOPL - 1] != 0ULL) unsafe = true;  // partition may hide more
                }
            }
        }
        if (lane < NL) s_ptr[lane] = ptr;
        if (lane == 0) {
            s_kcount = kc;
            s_fallback = fb;
            s_ctrl = fb ? 0 : 1;
        }
    }
    __syncthreads();

    // ---- Phase C: exact fallback — full lazy argmax over all keys (rare path) ----
    if (s_fallback) {
        for (int i = tid; i < n; i += K2T) s_keys[i] = pack_key(scores[i], i);
        __syncthreads();
        for (int i = tid; i < NL * TOPL; i += K2T) {         // kill already-consumed candidates
            int wl = i / TOPL, d = i % TOPL;
            if (d < s_ptr[wl]) {
                unsigned long long key = s_lists[i];
                if (key) s_keys[~(unsigned)(key & 0xFFFFFFFFu)] = 0ULL;
            }
        }
        __syncthreads();
        while (s_ctrl == 0) {
            unsigned long long best = 0ULL;
            for (int i = tid; i < n; i += K2T) {
                unsigned long long k = s_keys[i];
                if (k > best) best = k;
            }
            #pragma unroll
            for (int off = 16; off; off >>= 1) {
                unsigned long long o = __shfl_xor_sync(FULLM, best, off);
                if (o > best) best = o;
            }
            if (lane == 0) s_wmax[w] = best;
            __syncthreads();
            if (w == 0) {
                unsigned long long b = (lane < NW) ? s_wmax[lane] : 0ULL;
                #pragma unroll
                for (int off = 16; off; off >>= 1) {
                    unsigned long long o = __shfl_xor_sync(FULLM, b, off);
                    if (o > b) b = o;
                }
                b = __shfl_sync(FULLM, b, 0);
                if (b == 0ULL) {
                    if (lane == 0) s_ctrl = 1;
                } else {
                    int idx = ~(unsigned)(b & 0xFFFFFFFFu);
                    const float* row = prop + (long long)idx * ROWLEN;
                    float x0 = row[5 + lane];
                    float x1 = row[37 + lane];
                    float x2 = (lane < 8) ? row[69 + lane] : 0.f;
                    int si = 0, ei = 0;
                    if (lane == 0) {
                        si = (int)rintf(row[2] * (float)N_STRIPS);
                        ei = min(si + (int)rintf(row[4]) - 1, N_STRIPS);
                    }
                    si = __shfl_sync(FULLM, si, 0);
                    ei = __shfl_sync(FULLM, ei, 0);
                    int kc2 = s_kcount;
                    bool dead = false;
                    for (int m = 0; m < kc2 && !dead; ++m) {
                        int ps = max(si, s_ks[m]);
                        int pe = min(ei, s_ke[m]);
                        if (pe >= ps) {
                            float d = 0.f;
                            if (lane >= ps && lane <= pe)           d += fabsf(x0 - s_kxs[m][lane]);
                            if (lane + 32 >= ps && lane + 32 <= pe) d += fabsf(x1 - s_kxs[m][lane + 32]);
                            if (lane < 8 && lane + 64 >= ps && lane + 64 <= pe)
                                                                    d += fabsf(x2 - s_kxs[m][lane + 64]);
                            #pragma unroll
                            for (int off = 16; off; off >>= 1)
                                d += __shfl_xor_sync(FULLM, d, off);
                            int su = 0;
                            if (lane == 0) su = (d / (float)(pe - ps + 1) < thr) ? 1 : 0;
                            dead = __shfl_sync(FULLM, su, 0);
                        }
                    }
                    if (!dead) {
                        s_kxs[kc2][lane]      = x0;
                        s_kxs[kc2][lane + 32] = x1;
                        if (lane < 8) s_kxs[kc2][lane + 64] = x2;
                        if (lane == 0) {
                            s_ks[kc2] = si; s_ke[kc2] = ei; s_kidx[kc2] = idx;
                            s_kcount = kc2 + 1;
                            if (kc2 + 1 >= topk) s_ctrl = 1;
                        }
                    }
                    if (lane == 0) s_keys[idx] = 0ULL;
                }
            }
            __syncthreads();
        }
    }

    // ---- Phase D: output topk rows (77 floats + score) then num_kept ----
    int nk = min(s_kcount, topk);
    int total = topk * (ROWLEN + 1);
    for (int i = tid; i < out_size; i += K2T) {
        float v = 0.f;
        if (i < total) {
            int r   = i / (ROWLEN + 1);
            int cdx = i % (ROWLEN + 1);
            if (r < nk) {
                int idx = s_kidx[r];
                if (cdx < ROWLEN) v = prop[(long long)idx * ROWLEN + cdx];
                else              v = scores[idx];
            }
        } else if (i == total) {
            v = (float)nk;
        }
        out[i] = v;
    }
}

extern "C" void kernel_launch(void* const* d_in, const int* in_sizes, int n_in,
                              void* d_out, int out_size)
{
    const float*    prop   = (const float*)d_in[0];
    const float*    scores = (const float*)d_in[1];
    const unsigned* thr    = (const unsigned*)d_in[2];
    const unsigned* topk   = (const unsigned*)d_in[3];

    int n = in_sizes[1];
    int chunk = (n + NL - 1) / NL;
    int P = 1; while (P < chunk) P <<= 1;

    size_t smem1 = (size_t)P * sizeof(unsigned long long);
    cudaFuncSetAttribute(k1_partsort, cudaFuncAttributeMaxDynamicSharedMemorySize, (int)smem1);
    k1_partsort<<<NL, 256, smem1>>>(scores, n, chunk, P);

    size_t smem2 = (size_t)n * 8 + (size_t)NL * TOPL * 8
                 + ((size_t)NL * PREF * RPAD + RPAD) * sizeof(float);
    cudaFuncSetAttribute(k2_greedy, cudaFuncAttributeMaxDynamicSharedMemorySize, (int)smem2);
    k2_greedy<<<1, K2T, smem2>>>(prop, scores, thr, topk, (float*)d_out, n, out_size);
}